// round 10
// baseline (speedup 1.0000x reference)
#include <cuda_runtime.h>
#include <math.h>

#define BSZ 8
#define CH  1024
#define TT  1024
#define NH  16
#define HD  64
#define RD  32   // rope dim
#define RH  16   // rope half

// ---------------- scratch (device globals; no allocation allowed) ----------
__device__ float g_p[(size_t)BSZ * CH * TT];   // attn out (proj-input layout)
__device__ float g_q[(size_t)BSZ * CH * TT];   // [B,H,T,D]
__device__ float g_k[(size_t)BSZ * CH * TT];
__device__ float g_v[(size_t)BSZ * CH * TT];

// ---------------------------------------------------------------------------
__device__ __forceinline__ unsigned f2tf32(float x) {
  unsigned r;
  asm("cvt.rna.tf32.f32 %0, %1;" : "=r"(r) : "f"(x));
  return r;
}

__device__ __forceinline__ void mma_tf32(float c[4], unsigned a0, unsigned a1,
                                         unsigned a2, unsigned a3, unsigned b0,
                                         unsigned b1) {
  asm volatile(
      "mma.sync.aligned.m16n8k8.row.col.f32.tf32.tf32.f32 "
      "{%0,%1,%2,%3}, {%4,%5,%6,%7}, {%8,%9}, {%0,%1,%2,%3};"
      : "+f"(c[0]), "+f"(c[1]), "+f"(c[2]), "+f"(c[3])
      : "r"(a0), "r"(a1), "r"(a2), "r"(a3), "r"(b0), "r"(b1));
}

// ---------------------------------------------------------------------------
// TF32 tensor-core GEMM, 2-stage smem double buffering (1 sync per k-tile).
//   acc[b][m][n] = sum_k W[m][k] * X[b][k][n] + bias[m]
// mode 0: Out[B,C,T] = acc                       (final projection)
// mode 1: Out[B,H,T,D] = rope(acc) (transposed)  (Q, K)
// mode 2: Out[B,H,T,D] = acc       (transposed)  (V)
// grid (T/128, C/128, B), 256 threads (8 warps, 2m x 4n), warp tile 64x32.
// ---------------------------------------------------------------------------
#define GA (128 * 36)
#define GB (32 * 136)
#define GSM_BYTES ((2 * GA + 2 * GB) * 4)

__global__ void __launch_bounds__(256, 2) gemm_tf32(
    const float* __restrict__ W, const float* __restrict__ X,
    const float* __restrict__ bias, float* __restrict__ Out, int mode) {
  extern __shared__ unsigned dsm[];
  unsigned* const AsBuf[2] = {dsm, dsm + GA};
  unsigned* const BsBuf[2] = {dsm + 2 * GA, dsm + 2 * GA + GB};

  const float* Xb = X + (size_t)blockIdx.z * CH * TT;
  const int m0 = blockIdx.y * 128, n0 = blockIdx.x * 128;
  const int tid = threadIdx.x;
  const int warp = tid >> 5, lane = tid & 31;
  const int wm = warp & 1, wn = warp >> 1;
  const int g = lane >> 2, tg = lane & 3;

  const int am = tid >> 3;          // 0..31
  const int ak = (tid & 7) * 4;     // 0..28
  const int bk = tid >> 5;          // 0..7
  const int bn = (tid & 31) * 4;    // 0..124

  float acc[4][4][4];
#pragma unroll
  for (int i = 0; i < 4; i++)
#pragma unroll
    for (int j = 0; j < 4; j++)
#pragma unroll
      for (int r = 0; r < 4; r++) acc[i][j][r] = 0.0f;

  float4 wreg[4], xreg[4];
#pragma unroll
  for (int p = 0; p < 4; p++) {
    wreg[p] = *(const float4*)&W[(size_t)(m0 + p * 32 + am) * CH + ak];
    xreg[p] = *(const float4*)&Xb[(size_t)(p * 8 + bk) * TT + n0 + bn];
  }

  for (int kt = 0; kt < CH / 32; kt++) {
    unsigned* As = AsBuf[kt & 1];
    unsigned* Bs = BsBuf[kt & 1];
    // store held regs (tile kt) -> current buffer
#pragma unroll
    for (int p = 0; p < 4; p++) {
      int m = p * 32 + am;
      As[m * 36 + ak + 0] = f2tf32(wreg[p].x);
      As[m * 36 + ak + 1] = f2tf32(wreg[p].y);
      As[m * 36 + ak + 2] = f2tf32(wreg[p].z);
      As[m * 36 + ak + 3] = f2tf32(wreg[p].w);
      uint4 u;
      u.x = f2tf32(xreg[p].x); u.y = f2tf32(xreg[p].y);
      u.z = f2tf32(xreg[p].z); u.w = f2tf32(xreg[p].w);
      *(uint4*)&Bs[(p * 8 + bk) * 136 + bn] = u;
    }
    __syncthreads();

    // prefetch tile kt+1 (consumed next iteration; spans the MMA block)
    if (kt + 1 < CH / 32) {
      int k0 = (kt + 1) * 32;
#pragma unroll
      for (int p = 0; p < 4; p++) {
        wreg[p] =
            *(const float4*)&W[(size_t)(m0 + p * 32 + am) * CH + k0 + ak];
        xreg[p] =
            *(const float4*)&Xb[(size_t)(k0 + p * 8 + bk) * TT + n0 + bn];
      }
    }

#pragma unroll
    for (int ks = 0; ks < 4; ks++) {
      const int kk = ks * 8;
      unsigned a[4][4], b[4][2];
#pragma unroll
      for (int mi = 0; mi < 4; mi++) {
        int row = wm * 64 + mi * 16 + g;
        a[mi][0] = As[row * 36 + kk + tg];
        a[mi][1] = As[(row + 8) * 36 + kk + tg];
        a[mi][2] = As[row * 36 + kk + tg + 4];
        a[mi][3] = As[(row + 8) * 36 + kk + tg + 4];
      }
#pragma unroll
      for (int ni = 0; ni < 4; ni++) {
        int col = wn * 32 + ni * 8 + g;
        b[ni][0] = Bs[(kk + tg) * 136 + col];
        b[ni][1] = Bs[(kk + tg + 4) * 136 + col];
      }
#pragma unroll
      for (int mi = 0; mi < 4; mi++)
#pragma unroll
        for (int ni = 0; ni < 4; ni++)
          mma_tf32(acc[mi][ni], a[mi][0], a[mi][1], a[mi][2], a[mi][3],
                   b[ni][0], b[ni][1]);
    }
  }

  // ---- bias ----
#pragma unroll
  for (int mi = 0; mi < 4; mi++) {
    float bv0 = bias[m0 + wm * 64 + mi * 16 + g];
    float bv1 = bias[m0 + wm * 64 + mi * 16 + g + 8];
#pragma unroll
    for (int ni = 0; ni < 4; ni++) {
      acc[mi][ni][0] += bv0; acc[mi][ni][1] += bv0;
      acc[mi][ni][2] += bv1; acc[mi][ni][3] += bv1;
    }
  }

  if (mode == 0) {
    float* Ob = Out + (size_t)blockIdx.z * CH * TT;
#pragma unroll
    for (int mi = 0; mi < 4; mi++) {
      int row = m0 + wm * 64 + mi * 16 + g;
#pragma unroll
      for (int ni = 0; ni < 4; ni++) {
        int col = n0 + wn * 32 + ni * 8 + 2 * tg;
        *(float2*)&Ob[(size_t)row * TT + col] =
            make_float2(acc[mi][ni][0], acc[mi][ni][1]);
        *(float2*)&Ob[(size_t)(row + 8) * TT + col] =
            make_float2(acc[mi][ni][2], acc[mi][ni][3]);
      }
    }
    return;
  }

  // ---- fused RoPE (mode 1): pair (d, d+16) = (acc[0], acc[1]) rows ----
  if (mode == 1) {
    float th0 = powf(10000.0f, -(2.0f * g) / (float)RD);
    float th1 = powf(10000.0f, -(2.0f * (g + 8)) / (float)RD);
#pragma unroll
    for (int ni = 0; ni < 4; ni++) {
      int t0c = n0 + wn * 32 + ni * 8 + 2 * tg;
#pragma unroll
      for (int j = 0; j < 2; j++) {
        float t = (float)(t0c + j);
        float s, c;
        sincosf(t * th0, &s, &c);
        float x0 = acc[0][ni][j], x1 = acc[1][ni][j];
        acc[0][ni][j] = x0 * c - x1 * s;
        acc[1][ni][j] = x1 * c + x0 * s;
        sincosf(t * th1, &s, &c);
        float y0 = acc[0][ni][2 + j], y1 = acc[1][ni][2 + j];
        acc[0][ni][2 + j] = y0 * c - y1 * s;
        acc[1][ni][2 + j] = y1 * c + y0 * s;
      }
    }
  }

  // ---- transposed write to [B,H,T,D] ----
  {
    int head = blockIdx.y * 2 + wm;
    float* Oq = Out + ((size_t)blockIdx.z * NH + head) * TT * 64;
#pragma unroll
    for (int mi = 0; mi < 4; mi++) {
      int d = mi * 16 + g;
#pragma unroll
      for (int ni = 0; ni < 4; ni++) {
        int t = n0 + wn * 32 + ni * 8 + 2 * tg;
        Oq[(size_t)t * 64 + d] = acc[mi][ni][0];
        Oq[(size_t)(t + 1) * 64 + d] = acc[mi][ni][1];
        Oq[(size_t)t * 64 + d + 8] = acc[mi][ni][2];
        Oq[(size_t)(t + 1) * 64 + d + 8] = acc[mi][ni][3];
      }
    }
  }
}

// ---------------------------------------------------------------------------
// Tensor-core flash attention: 256 threads / 8 warps, 128 q-rows per CTA,
// shared 64-key K/V tile (halves staging traffic vs 4-warp version).
// Q,K,V: [B,H,T,D] fp32. AO: [B, h*64+d, T].
// grid (T/128, H, B).
// ---------------------------------------------------------------------------
#define ASTR 68
#define OSTR 136
// Ks[64*68] + Vs[64*68] + Ps[128*68] + bias[1024] + msk[64]
#define ATT_SMEM ((2 * 64 * ASTR + 128 * ASTR + 1024 + 64) * 4)

__global__ void __launch_bounds__(256, 2) attn_mma(
    const float* __restrict__ Q, const float* __restrict__ K,
    const float* __restrict__ V, const int* __restrict__ mask,
    float* __restrict__ AO) {
  extern __shared__ char smraw[];
  unsigned* Ks = (unsigned*)smraw;            // [64][ASTR]
  unsigned* Vs = Ks + 64 * ASTR;              // [64][ASTR]
  unsigned* Ps = Vs + 64 * ASTR;              // [128][ASTR]
  float* bias_t = (float*)(Ps + 128 * ASTR);  // [1024]
  int* msk = (int*)(bias_t + 1024);           // [64]
  float* Od = (float*)Ks;                     // [64][OSTR] output staging reuse

  const int tid = threadIdx.x;
  const int warp = tid >> 5, lane = tid & 31;
  const int g = lane >> 2, tg = lane & 3;
  const int b = blockIdx.z, h = blockIdx.y, q0 = blockIdx.x * 128;
  const size_t bh = (size_t)b * NH + h;
  const float* Qb = Q + (bh * TT + q0) * 64;
  const float* Kb = K + bh * TT * 64;
  const float* Vb = V + bh * TT * 64;
  const int* mb = mask + (size_t)b * TT;

  for (int i = tid; i < 1024; i += 256) bias_t[i] = -log1pf((float)i);

  // stage Q tile (128 rows, pre-scaled by 1/8, tf32) into Ps
#pragma unroll
  for (int i = 0; i < 8; i++) {
    int idx = i * 256 + tid;
    int row = idx >> 4, c4 = (idx & 15) * 4;
    float4 v4 = *(const float4*)&Qb[row * 64 + c4];
    uint4 u;
    u.x = f2tf32(v4.x * 0.125f); u.y = f2tf32(v4.y * 0.125f);
    u.z = f2tf32(v4.z * 0.125f); u.w = f2tf32(v4.w * 0.125f);
    *(uint4*)&Ps[row * ASTR + c4] = u;
  }
  __syncthreads();

  const int r0 = warp * 16 + g;   // local q-row (c0/c1); c2/c3: +8
  unsigned aq[8][4];
#pragma unroll
  for (int kc = 0; kc < 8; kc++) {
    aq[kc][0] = Ps[r0 * ASTR + kc * 8 + tg];
    aq[kc][1] = Ps[(r0 + 8) * ASTR + kc * 8 + tg];
    aq[kc][2] = Ps[r0 * ASTR + kc * 8 + tg + 4];
    aq[kc][3] = Ps[(r0 + 8) * ASTR + kc * 8 + tg + 4];
  }

  float accO[8][4];
#pragma unroll
  for (int nt = 0; nt < 8; nt++)
#pragma unroll
    for (int i = 0; i < 4; i++) accO[nt][i] = 0.0f;
  float m0r = -INFINITY, m1r = -INFINITY, l0r = 0.0f, l1r = 0.0f;
  const int trow0 = q0 + r0, trow1 = trow0 + 8;

  for (int k0 = 0; k0 < TT; k0 += 64) {
    __syncthreads();   // prev iter's Ks/Vs fragment reads done
#pragma unroll
    for (int i = 0; i < 4; i++) {
      int idx = i * 256 + tid;
      int row = idx >> 4, c4 = (idx & 15) * 4;
      float4 kv = *(const float4*)&Kb[(size_t)(k0 + row) * 64 + c4];
      uint4 uk;
      uk.x = f2tf32(kv.x); uk.y = f2tf32(kv.y);
      uk.z = f2tf32(kv.z); uk.w = f2tf32(kv.w);
      *(uint4*)&Ks[row * ASTR + c4] = uk;
      float4 vv = *(const float4*)&Vb[(size_t)(k0 + row) * 64 + c4];
      uint4 uv;
      uv.x = f2tf32(vv.x); uv.y = f2tf32(vv.y);
      uv.z = f2tf32(vv.z); uv.w = f2tf32(vv.w);
      *(uint4*)&Vs[row * ASTR + c4] = uv;
    }
    if (tid < 64) msk[tid] = mb[k0 + tid];
    __syncthreads();

    // S = Q * K^T (per warp: 16 x 64)
    float s[8][4];
#pragma unroll
    for (int nt = 0; nt < 8; nt++) {
      float c[4] = {0.0f, 0.0f, 0.0f, 0.0f};
#pragma unroll
      for (int kc = 0; kc < 8; kc++) {
        unsigned b0 = Ks[(nt * 8 + g) * ASTR + kc * 8 + tg];
        unsigned b1 = Ks[(nt * 8 + g) * ASTR + kc * 8 + tg + 4];
        mma_tf32(c, aq[kc][0], aq[kc][1], aq[kc][2], aq[kc][3], b0, b1);
      }
      int kl = nt * 8 + 2 * tg;
      int kA = k0 + kl;
      s[nt][0] = (msk[kl] == 0) ? -10000.0f : c[0] + bias_t[abs(trow0 - kA)];
      s[nt][1] = (msk[kl + 1] == 0) ? -10000.0f : c[1] + bias_t[abs(trow0 - kA - 1)];
      s[nt][2] = (msk[kl] == 0) ? -10000.0f : c[2] + bias_t[abs(trow1 - kA)];
      s[nt][3] = (msk[kl + 1] == 0) ? -10000.0f : c[3] + bias_t[abs(trow1 - kA - 1)];
    }

    float tm0 = -INFINITY, tm1 = -INFINITY;
#pragma unroll
    for (int nt = 0; nt < 8; nt++) {
      tm0 = fmaxf(tm0, fmaxf(s[nt][0], s[nt][1]));
      tm1 = fmaxf(tm1, fmaxf(s[nt][2], s[nt][3]));
    }
    tm0 = fmaxf(tm0, __shfl_xor_sync(0xffffffffu, tm0, 1));
    tm0 = fmaxf(tm0, __shfl_xor_sync(0xffffffffu, tm0, 2));
    tm1 = fmaxf(tm1, __shfl_xor_sync(0xffffffffu, tm1, 1));
    tm1 = fmaxf(tm1, __shfl_xor_sync(0xffffffffu, tm1, 2));
    float mn0 = fmaxf(m0r, tm0), mn1 = fmaxf(m1r, tm1);
    float sc0 = __expf(m0r - mn0), sc1 = __expf(m1r - mn1);
    m0r = mn0; m1r = mn1;

    float ps0 = 0.0f, ps1 = 0.0f;
#pragma unroll
    for (int nt = 0; nt < 8; nt++) {
      int col = nt * 8 + 2 * tg;
      float p0 = __expf(s[nt][0] - mn0);
      float p1 = __expf(s[nt][1] - mn0);
      float p2 = __expf(s[nt][2] - mn1);
      float p3 = __expf(s[nt][3] - mn1);
      ps0 += p0 + p1; ps1 += p2 + p3;
      Ps[r0 * ASTR + col] = f2tf32(p0);
      Ps[r0 * ASTR + col + 1] = f2tf32(p1);
      Ps[(r0 + 8) * ASTR + col] = f2tf32(p2);
      Ps[(r0 + 8) * ASTR + col + 1] = f2tf32(p3);
    }
    ps0 += __shfl_xor_sync(0xffffffffu, ps0, 1);
    ps0 += __shfl_xor_sync(0xffffffffu, ps0, 2);
    ps1 += __shfl_xor_sync(0xffffffffu, ps1, 1);
    ps1 += __shfl_xor_sync(0xffffffffu, ps1, 2);
    l0r = l0r * sc0 + ps0;
    l1r = l1r * sc1 + ps1;

#pragma unroll
    for (int nt = 0; nt < 8; nt++) {
      accO[nt][0] *= sc0; accO[nt][1] *= sc0;
      accO[nt][2] *= sc1; accO[nt][3] *= sc1;
    }

    __syncwarp();  // P rows are warp-private; order stores before reads

    // O += P * V
#pragma unroll
    for (int kc = 0; kc < 8; kc++) {
      unsigned a0 = Ps[r0 * ASTR + kc * 8 + tg];
      unsigned a1 = Ps[(r0 + 8) * ASTR + kc * 8 + tg];
      unsigned a2 = Ps[r0 * ASTR + kc * 8 + tg + 4];
      unsigned a3 = Ps[(r0 + 8) * ASTR + kc * 8 + tg + 4];
#pragma unroll
      for (int nt = 0; nt < 8; nt++) {
        unsigned b0 = Vs[(kc * 8 + tg) * ASTR + nt * 8 + g];
        unsigned b1 = Vs[(kc * 8 + tg + 4) * ASTR + nt * 8 + g];
        mma_tf32(accO[nt], a0, a1, a2, a3, b0, b1);
      }
    }
  }

  // stage output (d-major, 64 x OSTR over the Ks/Vs region) and write
  __syncthreads();
  float inv0 = 1.0f / l0r, inv1 = 1.0f / l1r;
#pragma unroll
  for (int nt = 0; nt < 8; nt++) {
    int d = nt * 8 + 2 * tg;
    Od[d * OSTR + r0] = accO[nt][0] * inv0;
    Od[(d + 1) * OSTR + r0] = accO[nt][1] * inv0;
    Od[d * OSTR + r0 + 8] = accO[nt][2] * inv1;
    Od[(d + 1) * OSTR + r0 + 8] = accO[nt][3] * inv1;
  }
  __syncthreads();
  {
    int d = tid >> 2;
    int c0 = (tid & 3) * 32;
    float* ao = AO + ((size_t)b * CH + (size_t)h * 64 + d) * TT + q0 + c0;
#pragma unroll
    for (int i = 0; i < 8; i++) {
      float4 o4 = *(float4*)&Od[d * OSTR + c0 + i * 4];
      *(float4*)&ao[i * 4] = o4;
    }
  }
}

// ---------------------------------------------------------------------------
extern "C" void kernel_launch(void* const* d_in, const int* in_sizes, int n_in,
                              void* d_out, int out_size) {
  const float* x    = (const float*)d_in[0];
  const float* ctx  = (const float*)d_in[1];
  const int*   mask = (const int*)d_in[2];
  const float* Wq   = (const float*)d_in[3];
  const float* bq   = (const float*)d_in[4];
  const float* Wk   = (const float*)d_in[5];
  const float* bk   = (const float*)d_in[6];
  const float* Wv   = (const float*)d_in[7];
  const float* bv   = (const float*)d_in[8];
  const float* Wo   = (const float*)d_in[9];
  const float* bo   = (const float*)d_in[10];
  float* out = (float*)d_out;

  float *p, *q, *k, *v;
  cudaGetSymbolAddress((void**)&p, g_p);
  cudaGetSymbolAddress((void**)&q, g_q);
  cudaGetSymbolAddress((void**)&k, g_k);
  cudaGetSymbolAddress((void**)&v, g_v);

  cudaFuncSetAttribute(gemm_tf32, cudaFuncAttributeMaxDynamicSharedMemorySize,
                       GSM_BYTES);
  cudaFuncSetAttribute(attn_mma, cudaFuncAttributeMaxDynamicSharedMemorySize,
                       ATT_SMEM);

  dim3 gg(TT / 128, CH / 128, BSZ);
  dim3 ag(TT / 128, NH, BSZ);

  gemm_tf32<<<gg, 256, GSM_BYTES>>>(Wq, x, bq, q, 1);
  gemm_tf32<<<gg, 256, GSM_BYTES>>>(Wk, ctx, bk, k, 1);
  gemm_tf32<<<gg, 256, GSM_BYTES>>>(Wv, ctx, bv, v, 2);
  attn_mma<<<ag, 256, ATT_SMEM>>>(q, k, v, mask, p);
  gemm_tf32<<<gg, 256, GSM_BYTES>>>(Wo, p, bo, out, 0);
}

// round 13
// speedup vs baseline: 1.2182x; 1.2182x over previous
#include <cuda_runtime.h>
#include <math.h>

#define BSZ 8
#define CH  1024
#define TT  1024
#define NH  16
#define HD  64
#define RD  32   // rope dim
#define RH  16   // rope half

// ---------------- scratch (device globals; no allocation allowed) ----------
__device__ float g_p[(size_t)BSZ * CH * TT];   // attn out (proj-input layout)
__device__ float g_q[(size_t)BSZ * CH * TT];   // [B,H,T,D]
__device__ float g_k[(size_t)BSZ * CH * TT];
__device__ float g_v[(size_t)BSZ * CH * TT];

// ---------------------------------------------------------------------------
__device__ __forceinline__ unsigned f2tf32(float x) {
  unsigned r;
  asm("cvt.rna.tf32.f32 %0, %1;" : "=r"(r) : "f"(x));
  return r;
}

__device__ __forceinline__ void mma_tf32(float c[4], unsigned a0, unsigned a1,
                                         unsigned a2, unsigned a3, unsigned b0,
                                         unsigned b1) {
  asm volatile(
      "mma.sync.aligned.m16n8k8.row.col.f32.tf32.tf32.f32 "
      "{%0,%1,%2,%3}, {%4,%5,%6,%7}, {%8,%9}, {%0,%1,%2,%3};"
      : "+f"(c[0]), "+f"(c[1]), "+f"(c[2]), "+f"(c[3])
      : "r"(a0), "r"(a1), "r"(a2), "r"(a3), "r"(b0), "r"(b1));
}

// ---------------------------------------------------------------------------
// TF32 tensor-core GEMM with register-prefetch double buffering (R4 version,
// measured-best GEMM config).
//   acc[b][m][n] = sum_k W[m][k] * X[b][k][n] + bias[m]
// mode 0: Out[B,C,T] = acc; mode 1: rope+transpose; mode 2: transpose.
// grid (T/128, C/128, B), 256 threads (8 warps, 2m x 4n), warp tile 64x32.
// ---------------------------------------------------------------------------
__global__ void __launch_bounds__(256) gemm_tf32(
    const float* __restrict__ W, const float* __restrict__ X,
    const float* __restrict__ bias, float* __restrict__ Out, int mode) {
  __shared__ unsigned As[128][36];
  __shared__ unsigned Bs[32][136];

  const float* Xb = X + (size_t)blockIdx.z * CH * TT;
  const int m0 = blockIdx.y * 128, n0 = blockIdx.x * 128;
  const int tid = threadIdx.x;
  const int warp = tid >> 5, lane = tid & 31;
  const int wm = warp & 1, wn = warp >> 1;
  const int g = lane >> 2, tg = lane & 3;

  const int am = tid >> 3;          // 0..31
  const int ak = (tid & 7) * 4;     // 0..28
  const int bk = tid >> 5;          // 0..7
  const int bn = (tid & 31) * 4;    // 0..124

  float acc[4][4][4];
#pragma unroll
  for (int i = 0; i < 4; i++)
#pragma unroll
    for (int j = 0; j < 4; j++)
#pragma unroll
      for (int r = 0; r < 4; r++) acc[i][j][r] = 0.0f;

  float4 wreg[4], xreg[4];
#pragma unroll
  for (int p = 0; p < 4; p++) {
    wreg[p] = *(const float4*)&W[(size_t)(m0 + p * 32 + am) * CH + ak];
    xreg[p] = *(const float4*)&Xb[(size_t)(p * 8 + bk) * TT + n0 + bn];
  }

  for (int k0 = 0; k0 < CH; k0 += 32) {
#pragma unroll
    for (int p = 0; p < 4; p++) {
      int m = p * 32 + am;
      As[m][ak + 0] = f2tf32(wreg[p].x);
      As[m][ak + 1] = f2tf32(wreg[p].y);
      As[m][ak + 2] = f2tf32(wreg[p].z);
      As[m][ak + 3] = f2tf32(wreg[p].w);
      int k = p * 8 + bk;
      uint4 u;
      u.x = f2tf32(xreg[p].x); u.y = f2tf32(xreg[p].y);
      u.z = f2tf32(xreg[p].z); u.w = f2tf32(xreg[p].w);
      *(uint4*)&Bs[k][bn] = u;
    }
    __syncthreads();

    if (k0 + 32 < CH) {
#pragma unroll
      for (int p = 0; p < 4; p++) {
        wreg[p] =
            *(const float4*)&W[(size_t)(m0 + p * 32 + am) * CH + k0 + 32 + ak];
        xreg[p] =
            *(const float4*)&Xb[(size_t)(k0 + 32 + p * 8 + bk) * TT + n0 + bn];
      }
    }

#pragma unroll
    for (int ks = 0; ks < 4; ks++) {
      const int kk = ks * 8;
      unsigned a[4][4], b[4][2];
#pragma unroll
      for (int mi = 0; mi < 4; mi++) {
        int row = wm * 64 + mi * 16 + g;
        a[mi][0] = As[row][kk + tg];
        a[mi][1] = As[row + 8][kk + tg];
        a[mi][2] = As[row][kk + tg + 4];
        a[mi][3] = As[row + 8][kk + tg + 4];
      }
#pragma unroll
      for (int ni = 0; ni < 4; ni++) {
        int col = wn * 32 + ni * 8 + g;
        b[ni][0] = Bs[kk + tg][col];
        b[ni][1] = Bs[kk + tg + 4][col];
      }
#pragma unroll
      for (int mi = 0; mi < 4; mi++)
#pragma unroll
        for (int ni = 0; ni < 4; ni++)
          mma_tf32(acc[mi][ni], a[mi][0], a[mi][1], a[mi][2], a[mi][3],
                   b[ni][0], b[ni][1]);
    }
    __syncthreads();
  }

  // ---- bias ----
#pragma unroll
  for (int mi = 0; mi < 4; mi++) {
    float bv0 = bias[m0 + wm * 64 + mi * 16 + g];
    float bv1 = bias[m0 + wm * 64 + mi * 16 + g + 8];
#pragma unroll
    for (int ni = 0; ni < 4; ni++) {
      acc[mi][ni][0] += bv0; acc[mi][ni][1] += bv0;
      acc[mi][ni][2] += bv1; acc[mi][ni][3] += bv1;
    }
  }

  if (mode == 0) {
    float* Ob = Out + (size_t)blockIdx.z * CH * TT;
#pragma unroll
    for (int mi = 0; mi < 4; mi++) {
      int row = m0 + wm * 64 + mi * 16 + g;
#pragma unroll
      for (int ni = 0; ni < 4; ni++) {
        int col = n0 + wn * 32 + ni * 8 + 2 * tg;
        *(float2*)&Ob[(size_t)row * TT + col] =
            make_float2(acc[mi][ni][0], acc[mi][ni][1]);
        *(float2*)&Ob[(size_t)(row + 8) * TT + col] =
            make_float2(acc[mi][ni][2], acc[mi][ni][3]);
      }
    }
    return;
  }

  if (mode == 1) {
    float th0 = powf(10000.0f, -(2.0f * g) / (float)RD);
    float th1 = powf(10000.0f, -(2.0f * (g + 8)) / (float)RD);
#pragma unroll
    for (int ni = 0; ni < 4; ni++) {
      int t0c = n0 + wn * 32 + ni * 8 + 2 * tg;
#pragma unroll
      for (int j = 0; j < 2; j++) {
        float t = (float)(t0c + j);
        float s, c;
        sincosf(t * th0, &s, &c);
        float x0 = acc[0][ni][j], x1 = acc[1][ni][j];
        acc[0][ni][j] = x0 * c - x1 * s;
        acc[1][ni][j] = x1 * c + x0 * s;
        sincosf(t * th1, &s, &c);
        float y0 = acc[0][ni][2 + j], y1 = acc[1][ni][2 + j];
        acc[0][ni][2 + j] = y0 * c - y1 * s;
        acc[1][ni][2 + j] = y1 * c + y0 * s;
      }
    }
  }

  {
    int head = blockIdx.y * 2 + wm;
    float* Oq = Out + ((size_t)blockIdx.z * NH + head) * TT * 64;
#pragma unroll
    for (int mi = 0; mi < 4; mi++) {
      int d = mi * 16 + g;
#pragma unroll
      for (int ni = 0; ni < 4; ni++) {
        int t = n0 + wn * 32 + ni * 8 + 2 * tg;
        Oq[(size_t)t * 64 + d] = acc[mi][ni][0];
        Oq[(size_t)(t + 1) * 64 + d] = acc[mi][ni][1];
        Oq[(size_t)t * 64 + d + 8] = acc[mi][ni][2];
        Oq[(size_t)(t + 1) * 64 + d + 8] = acc[mi][ni][3];
      }
    }
  }
}

// ---------------------------------------------------------------------------
// Tensor-core flash attention: 4 warps, 32 q-rows per warp (two 16-row
// m-sets sharing every K/V B-fragment -> B-frag LDS bytes halved), 128
// q-rows/CTA, 64-key tiles processed as two 32-key half-passes.
// Q,K,V: [B,H,T,D] fp32. AO: [B, h*64+d, T].  grid (T/128, H, B), 128 thr.
// ---------------------------------------------------------------------------
#define ASTR 68
#define OSTR 136
// Ks[64*68] + Vs[64*68] + Ps[128*68] + bias[1024] + msk[64]
#define ATT_SMEM ((2 * 64 * ASTR + 128 * ASTR + 1024 + 64) * 4)

__global__ void __launch_bounds__(128) attn_mma(
    const float* __restrict__ Q, const float* __restrict__ K,
    const float* __restrict__ V, const int* __restrict__ mask,
    float* __restrict__ AO) {
  extern __shared__ char smraw[];
  unsigned* Ks = (unsigned*)smraw;            // [64][ASTR]
  unsigned* Vs = Ks + 64 * ASTR;              // [64][ASTR]
  unsigned* Ps = Vs + 64 * ASTR;              // [128][ASTR] (Q then P)
  float* bias_t = (float*)(Ps + 128 * ASTR);  // [1024]
  int* msk = (int*)(bias_t + 1024);           // [64]
  float* Od = (float*)Ks;                     // [64][OSTR] output staging

  const int tid = threadIdx.x;
  const int warp = tid >> 5, lane = tid & 31;
  const int g = lane >> 2, tg = lane & 3;
  const int b = blockIdx.z, h = blockIdx.y, q0 = blockIdx.x * 128;
  const size_t bh = (size_t)b * NH + h;
  const float* Qb = Q + (bh * TT + q0) * 64;
  const float* Kb = K + bh * TT * 64;
  const float* Vb = V + bh * TT * 64;
  const int* mb = mask + (size_t)b * TT;

  for (int i = tid; i < 1024; i += 128) bias_t[i] = -log1pf((float)i);

  // stage Q tile (128 rows, pre-scaled by 1/8, tf32) into Ps
#pragma unroll
  for (int i = 0; i < 16; i++) {
    int idx = i * 128 + tid;
    int row = idx >> 4, c4 = (idx & 15) * 4;
    float4 v4 = *(const float4*)&Qb[row * 64 + c4];
    uint4 u;
    u.x = f2tf32(v4.x * 0.125f); u.y = f2tf32(v4.y * 0.125f);
    u.z = f2tf32(v4.z * 0.125f); u.w = f2tf32(v4.w * 0.125f);
    *(uint4*)&Ps[row * ASTR + c4] = u;
  }
  __syncthreads();

  // persistent Q fragments, both m-sets (Ps is overwritten by P later)
  unsigned aq[2][8][4];
#pragma unroll
  for (int set = 0; set < 2; set++) {
    int rq = warp * 32 + set * 16 + g;
#pragma unroll
    for (int kc = 0; kc < 8; kc++) {
      aq[set][kc][0] = Ps[rq * ASTR + kc * 8 + tg];
      aq[set][kc][1] = Ps[(rq + 8) * ASTR + kc * 8 + tg];
      aq[set][kc][2] = Ps[rq * ASTR + kc * 8 + tg + 4];
      aq[set][kc][3] = Ps[(rq + 8) * ASTR + kc * 8 + tg + 4];
    }
  }

  float accO[2][8][4];
#pragma unroll
  for (int set = 0; set < 2; set++)
#pragma unroll
    for (int nt = 0; nt < 8; nt++)
#pragma unroll
      for (int i = 0; i < 4; i++) accO[set][nt][i] = 0.0f;
  float mr[2][2] = {{-INFINITY, -INFINITY}, {-INFINITY, -INFINITY}};
  float lr[2][2] = {{0.0f, 0.0f}, {0.0f, 0.0f}};
  int trow[2][2];
#pragma unroll
  for (int set = 0; set < 2; set++) {
    trow[set][0] = q0 + warp * 32 + set * 16 + g;
    trow[set][1] = trow[set][0] + 8;
  }

  for (int k0 = 0; k0 < TT; k0 += 64) {
    __syncthreads();
#pragma unroll
    for (int i = 0; i < 8; i++) {
      int idx = i * 128 + tid;
      int row = idx >> 4, c4 = (idx & 15) * 4;
      float4 kv = *(const float4*)&Kb[(size_t)(k0 + row) * 64 + c4];
      uint4 uk;
      uk.x = f2tf32(kv.x); uk.y = f2tf32(kv.y);
      uk.z = f2tf32(kv.z); uk.w = f2tf32(kv.w);
      *(uint4*)&Ks[row * ASTR + c4] = uk;
      float4 vv = *(const float4*)&Vb[(size_t)(k0 + row) * 64 + c4];
      uint4 uv;
      uv.x = f2tf32(vv.x); uv.y = f2tf32(vv.y);
      uv.z = f2tf32(vv.z); uv.w = f2tf32(vv.w);
      *(uint4*)&Vs[row * ASTR + c4] = uv;
    }
    if (tid < 64) msk[tid] = mb[k0 + tid];
    __syncthreads();

#pragma unroll
    for (int h2 = 0; h2 < 2; h2++) {
      const int kh = h2 * 32;

      // S = Q*K^T for 32 keys, both m-sets sharing B fragments
      float s[2][4][4];
#pragma unroll
      for (int nt = 0; nt < 4; nt++) {
        float c0[4] = {0, 0, 0, 0}, c1[4] = {0, 0, 0, 0};
#pragma unroll
        for (int kc = 0; kc < 8; kc++) {
          unsigned b0 = Ks[(kh + nt * 8 + g) * ASTR + kc * 8 + tg];
          unsigned b1 = Ks[(kh + nt * 8 + g) * ASTR + kc * 8 + tg + 4];
          mma_tf32(c0, aq[0][kc][0], aq[0][kc][1], aq[0][kc][2], aq[0][kc][3],
                   b0, b1);
          mma_tf32(c1, aq[1][kc][0], aq[1][kc][1], aq[1][kc][2], aq[1][kc][3],
                   b0, b1);
        }
        int kl = kh + nt * 8 + 2 * tg;
        int kA = k0 + kl;
        bool z0 = (msk[kl] == 0), z1 = (msk[kl + 1] == 0);
        s[0][nt][0] = z0 ? -10000.0f : c0[0] + bias_t[abs(trow[0][0] - kA)];
        s[0][nt][1] = z1 ? -10000.0f : c0[1] + bias_t[abs(trow[0][0] - kA - 1)];
        s[0][nt][2] = z0 ? -10000.0f : c0[2] + bias_t[abs(trow[0][1] - kA)];
        s[0][nt][3] = z1 ? -10000.0f : c0[3] + bias_t[abs(trow[0][1] - kA - 1)];
        s[1][nt][0] = z0 ? -10000.0f : c1[0] + bias_t[abs(trow[1][0] - kA)];
        s[1][nt][1] = z1 ? -10000.0f : c1[1] + bias_t[abs(trow[1][0] - kA - 1)];
        s[1][nt][2] = z0 ? -10000.0f : c1[2] + bias_t[abs(trow[1][1] - kA)];
        s[1][nt][3] = z1 ? -10000.0f : c1[3] + bias_t[abs(trow[1][1] - kA - 1)];
      }

      // online softmax per m-set; P -> Ps (tf32)
#pragma unroll
      for (int set = 0; set < 2; set++) {
        float tm0 = -INFINITY, tm1 = -INFINITY;
#pragma unroll
        for (int nt = 0; nt < 4; nt++) {
          tm0 = fmaxf(tm0, fmaxf(s[set][nt][0], s[set][nt][1]));
          tm1 = fmaxf(tm1, fmaxf(s[set][nt][2], s[set][nt][3]));
        }
        tm0 = fmaxf(tm0, __shfl_xor_sync(0xffffffffu, tm0, 1));
        tm0 = fmaxf(tm0, __shfl_xor_sync(0xffffffffu, tm0, 2));
        tm1 = fmaxf(tm1, __shfl_xor_sync(0xffffffffu, tm1, 1));
        tm1 = fmaxf(tm1, __shfl_xor_sync(0xffffffffu, tm1, 2));
        float mn0 = fmaxf(mr[set][0], tm0), mn1 = fmaxf(mr[set][1], tm1);
        float sc0 = __expf(mr[set][0] - mn0), sc1 = __expf(mr[set][1] - mn1);
        mr[set][0] = mn0; mr[set][1] = mn1;

        int rq = warp * 32 + set * 16 + g;
        float ps0 = 0.0f, ps1 = 0.0f;
#pragma unroll
        for (int nt = 0; nt < 4; nt++) {
          int col = kh + nt * 8 + 2 * tg;
          float p0 = __expf(s[set][nt][0] - mn0);
          float p1 = __expf(s[set][nt][1] - mn0);
          float p2 = __expf(s[set][nt][2] - mn1);
          float p3 = __expf(s[set][nt][3] - mn1);
          ps0 += p0 + p1; ps1 += p2 + p3;
          Ps[rq * ASTR + col] = f2tf32(p0);
          Ps[rq * ASTR + col + 1] = f2tf32(p1);
          Ps[(rq + 8) * ASTR + col] = f2tf32(p2);
          Ps[(rq + 8) * ASTR + col + 1] = f2tf32(p3);
        }
        ps0 += __shfl_xor_sync(0xffffffffu, ps0, 1);
        ps0 += __shfl_xor_sync(0xffffffffu, ps0, 2);
        ps1 += __shfl_xor_sync(0xffffffffu, ps1, 1);
        ps1 += __shfl_xor_sync(0xffffffffu, ps1, 2);
        lr[set][0] = lr[set][0] * sc0 + ps0;
        lr[set][1] = lr[set][1] * sc1 + ps1;

#pragma unroll
        for (int nt = 0; nt < 8; nt++) {
          accO[set][nt][0] *= sc0; accO[set][nt][1] *= sc0;
          accO[set][nt][2] *= sc1; accO[set][nt][3] *= sc1;
        }
      }

      __syncwarp();  // P rows warp-private; order stores before frag reads

      // O += P * V (32 keys), both m-sets share V B-fragments
#pragma unroll
      for (int kc = 0; kc < 4; kc++) {
        int kcol = kh + kc * 8;
        unsigned pa[2][4];
#pragma unroll
        for (int set = 0; set < 2; set++) {
          int rq = warp * 32 + set * 16 + g;
          pa[set][0] = Ps[rq * ASTR + kcol + tg];
          pa[set][1] = Ps[(rq + 8) * ASTR + kcol + tg];
          pa[set][2] = Ps[rq * ASTR + kcol + tg + 4];
          pa[set][3] = Ps[(rq + 8) * ASTR + kcol + tg + 4];
        }
#pragma unroll
        for (int nt = 0; nt < 8; nt++) {
          unsigned b0 = Vs[(kcol + tg) * ASTR + nt * 8 + g];
          unsigned b1 = Vs[(kcol + tg + 4) * ASTR + nt * 8 + g];
          mma_tf32(accO[0][nt], pa[0][0], pa[0][1], pa[0][2], pa[0][3], b0, b1);
          mma_tf32(accO[1][nt], pa[1][0], pa[1][1], pa[1][2], pa[1][3], b0, b1);
        }
      }
    }
  }

  // stage output (d-major) and write coalesced along t
  __syncthreads();
#pragma unroll
  for (int set = 0; set < 2; set++) {
    float inv0 = 1.0f / lr[set][0], inv1 = 1.0f / lr[set][1];
    int rq = warp * 32 + set * 16 + g;
#pragma unroll
    for (int nt = 0; nt < 8; nt++) {
      int d = nt * 8 + 2 * tg;
      Od[d * OSTR + rq] = accO[set][nt][0] * inv0;
      Od[(d + 1) * OSTR + rq] = accO[set][nt][1] * inv0;
      Od[d * OSTR + rq + 8] = accO[set][nt][2] * inv1;
      Od[(d + 1) * OSTR + rq + 8] = accO[set][nt][3] * inv1;
    }
  }
  __syncthreads();
  {
    int d = tid >> 1;
    int c0 = (tid & 1) * 64;
    float* ao = AO + ((size_t)b * CH + (size_t)h * 64 + d) * TT + q0 + c0;
#pragma unroll
    for (int i = 0; i < 16; i++) {
      float4 o4 = *(float4*)&Od[d * OSTR + c0 + i * 4];
      *(float4*)&ao[i * 4] = o4;
    }
  }
}

// ---------------------------------------------------------------------------
extern "C" void kernel_launch(void* const* d_in, const int* in_sizes, int n_in,
                              void* d_out, int out_size) {
  const float* x    = (const float*)d_in[0];
  const float* ctx  = (const float*)d_in[1];
  const int*   mask = (const int*)d_in[2];
  const float* Wq   = (const float*)d_in[3];
  const float* bq   = (const float*)d_in[4];
  const float* Wk   = (const float*)d_in[5];
  const float* bk   = (const float*)d_in[6];
  const float* Wv   = (const float*)d_in[7];
  const float* bv   = (const float*)d_in[8];
  const float* Wo   = (const float*)d_in[9];
  const float* bo   = (const float*)d_in[10];
  float* out = (float*)d_out;

  float *p, *q, *k, *v;
  cudaGetSymbolAddress((void**)&p, g_p);
  cudaGetSymbolAddress((void**)&q, g_q);
  cudaGetSymbolAddress((void**)&k, g_k);
  cudaGetSymbolAddress((void**)&v, g_v);

  cudaFuncSetAttribute(attn_mma, cudaFuncAttributeMaxDynamicSharedMemorySize,
                       ATT_SMEM);

  dim3 gg(TT / 128, CH / 128, BSZ);
  dim3 ag(TT / 128, NH, BSZ);

  gemm_tf32<<<gg, 256>>>(Wq, x, bq, q, 1);     // Q proj + rope + transpose
  gemm_tf32<<<gg, 256>>>(Wk, ctx, bk, k, 1);   // K proj + rope + transpose
  gemm_tf32<<<gg, 256>>>(Wv, ctx, bv, v, 2);   // V proj + transpose
  attn_mma<<<ag, 128, ATT_SMEM>>>(q, k, v, mask, p);
  gemm_tf32<<<gg, 256>>>(Wo, p, bo, out, 0);   // output projection
}

// round 15
// speedup vs baseline: 1.2896x; 1.0586x over previous
#include <cuda_runtime.h>
#include <math.h>

#define BSZ 8
#define CH  1024
#define TT  1024
#define NH  16
#define HD  64
#define RD  32   // rope dim
#define RH  16   // rope half

// ---------------- scratch (device globals; no allocation allowed) ----------
__device__ float g_p[(size_t)BSZ * CH * TT];   // attn out (proj-input layout)
__device__ float g_q[(size_t)BSZ * CH * TT];   // [B,H,T,D]
__device__ float g_k[(size_t)BSZ * CH * TT];
__device__ float g_v[(size_t)BSZ * CH * TT];

// ---------------------------------------------------------------------------
__device__ __forceinline__ unsigned f2tf32(float x) {
  unsigned r;
  asm("cvt.rna.tf32.f32 %0, %1;" : "=r"(r) : "f"(x));
  return r;
}

__device__ __forceinline__ void mma_tf32(float c[4], unsigned a0, unsigned a1,
                                         unsigned a2, unsigned a3, unsigned b0,
                                         unsigned b1) {
  asm volatile(
      "mma.sync.aligned.m16n8k8.row.col.f32.tf32.tf32.f32 "
      "{%0,%1,%2,%3}, {%4,%5,%6,%7}, {%8,%9}, {%0,%1,%2,%3};"
      : "+f"(c[0]), "+f"(c[1]), "+f"(c[2]), "+f"(c[3])
      : "r"(a0), "r"(a1), "r"(a2), "r"(a3), "r"(b0), "r"(b1));
}

// ---------------------------------------------------------------------------
// Shared GEMM body (R13 measured-best internals, bit-identical).
//   acc[m][n] = sum_k W[m][k] * Xb[k][n] + bias[m]
// mode 0: Out[B,C,T] (uses bIdx); mode 1: rope+transpose to [B,H,T,D];
// mode 2: transpose to [B,H,T,D].
// blockIdx.x: n-tile, blockIdx.y: m-tile. 256 thr, warp tile 64x32.
// ---------------------------------------------------------------------------
__device__ __forceinline__ void gemm_body(
    const float* __restrict__ W, const float* __restrict__ Xb,
    const float* __restrict__ bias, float* __restrict__ Out, int mode,
    int bIdx) {
  __shared__ unsigned As[128][36];
  __shared__ unsigned Bs[32][136];

  const int m0 = blockIdx.y * 128, n0 = blockIdx.x * 128;
  const int tid = threadIdx.x;
  const int warp = tid >> 5, lane = tid & 31;
  const int wm = warp & 1, wn = warp >> 1;
  const int g = lane >> 2, tg = lane & 3;

  const int am = tid >> 3;          // 0..31
  const int ak = (tid & 7) * 4;     // 0..28
  const int bk = tid >> 5;          // 0..7
  const int bn = (tid & 31) * 4;    // 0..124

  float acc[4][4][4];
#pragma unroll
  for (int i = 0; i < 4; i++)
#pragma unroll
    for (int j = 0; j < 4; j++)
#pragma unroll
      for (int r = 0; r < 4; r++) acc[i][j][r] = 0.0f;

  float4 wreg[4], xreg[4];
#pragma unroll
  for (int p = 0; p < 4; p++) {
    wreg[p] = *(const float4*)&W[(size_t)(m0 + p * 32 + am) * CH + ak];
    xreg[p] = *(const float4*)&Xb[(size_t)(p * 8 + bk) * TT + n0 + bn];
  }

  for (int k0 = 0; k0 < CH; k0 += 32) {
#pragma unroll
    for (int p = 0; p < 4; p++) {
      int m = p * 32 + am;
      As[m][ak + 0] = f2tf32(wreg[p].x);
      As[m][ak + 1] = f2tf32(wreg[p].y);
      As[m][ak + 2] = f2tf32(wreg[p].z);
      As[m][ak + 3] = f2tf32(wreg[p].w);
      int k = p * 8 + bk;
      uint4 u;
      u.x = f2tf32(xreg[p].x); u.y = f2tf32(xreg[p].y);
      u.z = f2tf32(xreg[p].z); u.w = f2tf32(xreg[p].w);
      *(uint4*)&Bs[k][bn] = u;
    }
    __syncthreads();

    if (k0 + 32 < CH) {
#pragma unroll
      for (int p = 0; p < 4; p++) {
        wreg[p] =
            *(const float4*)&W[(size_t)(m0 + p * 32 + am) * CH + k0 + 32 + ak];
        xreg[p] =
            *(const float4*)&Xb[(size_t)(k0 + 32 + p * 8 + bk) * TT + n0 + bn];
      }
    }

#pragma unroll
    for (int ks = 0; ks < 4; ks++) {
      const int kk = ks * 8;
      unsigned a[4][4], b[4][2];
#pragma unroll
      for (int mi = 0; mi < 4; mi++) {
        int row = wm * 64 + mi * 16 + g;
        a[mi][0] = As[row][kk + tg];
        a[mi][1] = As[row + 8][kk + tg];
        a[mi][2] = As[row][kk + tg + 4];
        a[mi][3] = As[row + 8][kk + tg + 4];
      }
#pragma unroll
      for (int ni = 0; ni < 4; ni++) {
        int col = wn * 32 + ni * 8 + g;
        b[ni][0] = Bs[kk + tg][col];
        b[ni][1] = Bs[kk + tg + 4][col];
      }
#pragma unroll
      for (int mi = 0; mi < 4; mi++)
#pragma unroll
        for (int ni = 0; ni < 4; ni++)
          mma_tf32(acc[mi][ni], a[mi][0], a[mi][1], a[mi][2], a[mi][3],
                   b[ni][0], b[ni][1]);
    }
    __syncthreads();
  }

  // ---- bias ----
#pragma unroll
  for (int mi = 0; mi < 4; mi++) {
    float bv0 = bias[m0 + wm * 64 + mi * 16 + g];
    float bv1 = bias[m0 + wm * 64 + mi * 16 + g + 8];
#pragma unroll
    for (int ni = 0; ni < 4; ni++) {
      acc[mi][ni][0] += bv0; acc[mi][ni][1] += bv0;
      acc[mi][ni][2] += bv1; acc[mi][ni][3] += bv1;
    }
  }

  if (mode == 0) {
    float* Ob = Out + (size_t)bIdx * CH * TT;
#pragma unroll
    for (int mi = 0; mi < 4; mi++) {
      int row = m0 + wm * 64 + mi * 16 + g;
#pragma unroll
      for (int ni = 0; ni < 4; ni++) {
        int col = n0 + wn * 32 + ni * 8 + 2 * tg;
        *(float2*)&Ob[(size_t)row * TT + col] =
            make_float2(acc[mi][ni][0], acc[mi][ni][1]);
        *(float2*)&Ob[(size_t)(row + 8) * TT + col] =
            make_float2(acc[mi][ni][2], acc[mi][ni][3]);
      }
    }
    return;
  }

  if (mode == 1) {
    float th0 = powf(10000.0f, -(2.0f * g) / (float)RD);
    float th1 = powf(10000.0f, -(2.0f * (g + 8)) / (float)RD);
#pragma unroll
    for (int ni = 0; ni < 4; ni++) {
      int t0c = n0 + wn * 32 + ni * 8 + 2 * tg;
#pragma unroll
      for (int j = 0; j < 2; j++) {
        float t = (float)(t0c + j);
        float s, c;
        sincosf(t * th0, &s, &c);
        float x0 = acc[0][ni][j], x1 = acc[1][ni][j];
        acc[0][ni][j] = x0 * c - x1 * s;
        acc[1][ni][j] = x1 * c + x0 * s;
        sincosf(t * th1, &s, &c);
        float y0 = acc[0][ni][2 + j], y1 = acc[1][ni][2 + j];
        acc[0][ni][2 + j] = y0 * c - y1 * s;
        acc[1][ni][2 + j] = y1 * c + y0 * s;
      }
    }
  }

  {
    int head = blockIdx.y * 2 + wm;
    float* Oq = Out + ((size_t)bIdx * NH + head) * TT * 64;
#pragma unroll
    for (int mi = 0; mi < 4; mi++) {
      int d = mi * 16 + g;
#pragma unroll
      for (int ni = 0; ni < 4; ni++) {
        int t = n0 + wn * 32 + ni * 8 + 2 * tg;
        Oq[(size_t)t * 64 + d] = acc[mi][ni][0];
        Oq[(size_t)(t + 1) * 64 + d] = acc[mi][ni][1];
        Oq[(size_t)t * 64 + d + 8] = acc[mi][ni][2];
        Oq[(size_t)(t + 1) * 64 + d + 8] = acc[mi][ni][3];
      }
    }
  }
}

// ---------------------------------------------------------------------------
// Merged Q/K/V projection launch: grid.z = BSZ*3, z = b*3 + {0:K, 1:V, 2:Q}.
// K,V of the same batch are z-adjacent -> co-resident CTAs share ctx X tiles
// in L2. One launch = one tail wave instead of three.
// ---------------------------------------------------------------------------
__global__ void __launch_bounds__(256) gemm_qkv(
    const float* __restrict__ x, const float* __restrict__ ctx,
    const float* __restrict__ Wq, const float* __restrict__ bq,
    const float* __restrict__ Wk, const float* __restrict__ bk,
    const float* __restrict__ Wv, const float* __restrict__ bv,
    float* __restrict__ q, float* __restrict__ k, float* __restrict__ v) {
  const int z = blockIdx.z;
  const int b = z / 3, which = z - 3 * b;
  if (which == 0) {
    gemm_body(Wk, ctx + (size_t)b * CH * TT, bk, k, 1, b);
  } else if (which == 1) {
    gemm_body(Wv, ctx + (size_t)b * CH * TT, bv, v, 2, b);
  } else {
    gemm_body(Wq, x + (size_t)b * CH * TT, bq, q, 1, b);
  }
}

// Output projection (mode 0), grid.z = B.
__global__ void __launch_bounds__(256) gemm_o(
    const float* __restrict__ W, const float* __restrict__ X,
    const float* __restrict__ bias, float* __restrict__ Out) {
  gemm_body(W, X + (size_t)blockIdx.z * CH * TT, bias, Out, 0, blockIdx.z);
}

// ---------------------------------------------------------------------------
// Tensor-core flash attention (R13 measured-best): 4 warps, 32 q-rows/warp
// (two 16-row m-sets sharing every K/V B-fragment), 128 q-rows/CTA,
// 64-key tiles processed as two 32-key half-passes.
// Q,K,V: [B,H,T,D] fp32. AO: [B, h*64+d, T].  grid (T/128, H, B), 128 thr.
// ---------------------------------------------------------------------------
#define ASTR 68
#define OSTR 136
#define ATT_SMEM ((2 * 64 * ASTR + 128 * ASTR + 1024 + 64) * 4)

__global__ void __launch_bounds__(128) attn_mma(
    const float* __restrict__ Q, const float* __restrict__ K,
    const float* __restrict__ V, const int* __restrict__ mask,
    float* __restrict__ AO) {
  extern __shared__ char smraw[];
  unsigned* Ks = (unsigned*)smraw;            // [64][ASTR]
  unsigned* Vs = Ks + 64 * ASTR;              // [64][ASTR]
  unsigned* Ps = Vs + 64 * ASTR;              // [128][ASTR] (Q then P)
  float* bias_t = (float*)(Ps + 128 * ASTR);  // [1024]
  int* msk = (int*)(bias_t + 1024);           // [64]
  float* Od = (float*)Ks;                     // [64][OSTR] output staging

  const int tid = threadIdx.x;
  const int warp = tid >> 5, lane = tid & 31;
  const int g = lane >> 2, tg = lane & 3;
  const int b = blockIdx.z, h = blockIdx.y, q0 = blockIdx.x * 128;
  const size_t bh = (size_t)b * NH + h;
  const float* Qb = Q + (bh * TT + q0) * 64;
  const float* Kb = K + bh * TT * 64;
  const float* Vb = V + bh * TT * 64;
  const int* mb = mask + (size_t)b * TT;

  for (int i = tid; i < 1024; i += 128) bias_t[i] = -log1pf((float)i);

#pragma unroll
  for (int i = 0; i < 16; i++) {
    int idx = i * 128 + tid;
    int row = idx >> 4, c4 = (idx & 15) * 4;
    float4 v4 = *(const float4*)&Qb[row * 64 + c4];
    uint4 u;
    u.x = f2tf32(v4.x * 0.125f); u.y = f2tf32(v4.y * 0.125f);
    u.z = f2tf32(v4.z * 0.125f); u.w = f2tf32(v4.w * 0.125f);
    *(uint4*)&Ps[row * ASTR + c4] = u;
  }
  __syncthreads();

  unsigned aq[2][8][4];
#pragma unroll
  for (int set = 0; set < 2; set++) {
    int rq = warp * 32 + set * 16 + g;
#pragma unroll
    for (int kc = 0; kc < 8; kc++) {
      aq[set][kc][0] = Ps[rq * ASTR + kc * 8 + tg];
      aq[set][kc][1] = Ps[(rq + 8) * ASTR + kc * 8 + tg];
      aq[set][kc][2] = Ps[rq * ASTR + kc * 8 + tg + 4];
      aq[set][kc][3] = Ps[(rq + 8) * ASTR + kc * 8 + tg + 4];
    }
  }

  float accO[2][8][4];
#pragma unroll
  for (int set = 0; set < 2; set++)
#pragma unroll
    for (int nt = 0; nt < 8; nt++)
#pragma unroll
      for (int i = 0; i < 4; i++) accO[set][nt][i] = 0.0f;
  float mr[2][2] = {{-INFINITY, -INFINITY}, {-INFINITY, -INFINITY}};
  float lr[2][2] = {{0.0f, 0.0f}, {0.0f, 0.0f}};
  int trow[2][2];
#pragma unroll
  for (int set = 0; set < 2; set++) {
    trow[set][0] = q0 + warp * 32 + set * 16 + g;
    trow[set][1] = trow[set][0] + 8;
  }

  for (int k0 = 0; k0 < TT; k0 += 64) {
    __syncthreads();
#pragma unroll
    for (int i = 0; i < 8; i++) {
      int idx = i * 128 + tid;
      int row = idx >> 4, c4 = (idx & 15) * 4;
      float4 kv = *(const float4*)&Kb[(size_t)(k0 + row) * 64 + c4];
      uint4 uk;
      uk.x = f2tf32(kv.x); uk.y = f2tf32(kv.y);
      uk.z = f2tf32(kv.z); uk.w = f2tf32(kv.w);
      *(uint4*)&Ks[row * ASTR + c4] = uk;
      float4 vv = *(const float4*)&Vb[(size_t)(k0 + row) * 64 + c4];
      uint4 uv;
      uv.x = f2tf32(vv.x); uv.y = f2tf32(vv.y);
      uv.z = f2tf32(vv.z); uv.w = f2tf32(vv.w);
      *(uint4*)&Vs[row * ASTR + c4] = uv;
    }
    if (tid < 64) msk[tid] = mb[k0 + tid];
    __syncthreads();

#pragma unroll
    for (int h2 = 0; h2 < 2; h2++) {
      const int kh = h2 * 32;

      float s[2][4][4];
#pragma unroll
      for (int nt = 0; nt < 4; nt++) {
        float c0[4] = {0, 0, 0, 0}, c1[4] = {0, 0, 0, 0};
#pragma unroll
        for (int kc = 0; kc < 8; kc++) {
          unsigned b0 = Ks[(kh + nt * 8 + g) * ASTR + kc * 8 + tg];
          unsigned b1 = Ks[(kh + nt * 8 + g) * ASTR + kc * 8 + tg + 4];
          mma_tf32(c0, aq[0][kc][0], aq[0][kc][1], aq[0][kc][2], aq[0][kc][3],
                   b0, b1);
          mma_tf32(c1, aq[1][kc][0], aq[1][kc][1], aq[1][kc][2], aq[1][kc][3],
                   b0, b1);
        }
        int kl = kh + nt * 8 + 2 * tg;
        int kA = k0 + kl;
        bool z0 = (msk[kl] == 0), z1 = (msk[kl + 1] == 0);
        s[0][nt][0] = z0 ? -10000.0f : c0[0] + bias_t[abs(trow[0][0] - kA)];
        s[0][nt][1] = z1 ? -10000.0f : c0[1] + bias_t[abs(trow[0][0] - kA - 1)];
        s[0][nt][2] = z0 ? -10000.0f : c0[2] + bias_t[abs(trow[0][1] - kA)];
        s[0][nt][3] = z1 ? -10000.0f : c0[3] + bias_t[abs(trow[0][1] - kA - 1)];
        s[1][nt][0] = z0 ? -10000.0f : c1[0] + bias_t[abs(trow[1][0] - kA)];
        s[1][nt][1] = z1 ? -10000.0f : c1[1] + bias_t[abs(trow[1][0] - kA - 1)];
        s[1][nt][2] = z0 ? -10000.0f : c1[2] + bias_t[abs(trow[1][1] - kA)];
        s[1][nt][3] = z1 ? -10000.0f : c1[3] + bias_t[abs(trow[1][1] - kA - 1)];
      }

#pragma unroll
      for (int set = 0; set < 2; set++) {
        float tm0 = -INFINITY, tm1 = -INFINITY;
#pragma unroll
        for (int nt = 0; nt < 4; nt++) {
          tm0 = fmaxf(tm0, fmaxf(s[set][nt][0], s[set][nt][1]));
          tm1 = fmaxf(tm1, fmaxf(s[set][nt][2], s[set][nt][3]));
        }
        tm0 = fmaxf(tm0, __shfl_xor_sync(0xffffffffu, tm0, 1));
        tm0 = fmaxf(tm0, __shfl_xor_sync(0xffffffffu, tm0, 2));
        tm1 = fmaxf(tm1, __shfl_xor_sync(0xffffffffu, tm1, 1));
        tm1 = fmaxf(tm1, __shfl_xor_sync(0xffffffffu, tm1, 2));
        float mn0 = fmaxf(mr[set][0], tm0), mn1 = fmaxf(mr[set][1], tm1);
        float sc0 = __expf(mr[set][0] - mn0), sc1 = __expf(mr[set][1] - mn1);
        mr[set][0] = mn0; mr[set][1] = mn1;

        int rq = warp * 32 + set * 16 + g;
        float ps0 = 0.0f, ps1 = 0.0f;
#pragma unroll
        for (int nt = 0; nt < 4; nt++) {
          int col = kh + nt * 8 + 2 * tg;
          float p0 = __expf(s[set][nt][0] - mn0);
          float p1 = __expf(s[set][nt][1] - mn0);
          float p2 = __expf(s[set][nt][2] - mn1);
          float p3 = __expf(s[set][nt][3] - mn1);
          ps0 += p0 + p1; ps1 += p2 + p3;
          Ps[rq * ASTR + col] = f2tf32(p0);
          Ps[rq * ASTR + col + 1] = f2tf32(p1);
          Ps[(rq + 8) * ASTR + col] = f2tf32(p2);
          Ps[(rq + 8) * ASTR + col + 1] = f2tf32(p3);
        }
        ps0 += __shfl_xor_sync(0xffffffffu, ps0, 1);
        ps0 += __shfl_xor_sync(0xffffffffu, ps0, 2);
        ps1 += __shfl_xor_sync(0xffffffffu, ps1, 1);
        ps1 += __shfl_xor_sync(0xffffffffu, ps1, 2);
        lr[set][0] = lr[set][0] * sc0 + ps0;
        lr[set][1] = lr[set][1] * sc1 + ps1;

#pragma unroll
        for (int nt = 0; nt < 8; nt++) {
          accO[set][nt][0] *= sc0; accO[set][nt][1] *= sc0;
          accO[set][nt][2] *= sc1; accO[set][nt][3] *= sc1;
        }
      }

      __syncwarp();

#pragma unroll
      for (int kc = 0; kc < 4; kc++) {
        int kcol = kh + kc * 8;
        unsigned pa[2][4];
#pragma unroll
        for (int set = 0; set < 2; set++) {
          int rq = warp * 32 + set * 16 + g;
          pa[set][0] = Ps[rq * ASTR + kcol + tg];
          pa[set][1] = Ps[(rq + 8) * ASTR + kcol + tg];
          pa[set][2] = Ps[rq * ASTR + kcol + tg + 4];
          pa[set][3] = Ps[(rq + 8) * ASTR + kcol + tg + 4];
        }
#pragma unroll
        for (int nt = 0; nt < 8; nt++) {
          unsigned b0 = Vs[(kcol + tg) * ASTR + nt * 8 + g];
          unsigned b1 = Vs[(kcol + tg + 4) * ASTR + nt * 8 + g];
          mma_tf32(accO[0][nt], pa[0][0], pa[0][1], pa[0][2], pa[0][3], b0, b1);
          mma_tf32(accO[1][nt], pa[1][0], pa[1][1], pa[1][2], pa[1][3], b0, b1);
        }
      }
    }
  }

  __syncthreads();
#pragma unroll
  for (int set = 0; set < 2; set++) {
    float inv0 = 1.0f / lr[set][0], inv1 = 1.0f / lr[set][1];
    int rq = warp * 32 + set * 16 + g;
#pragma unroll
    for (int nt = 0; nt < 8; nt++) {
      int d = nt * 8 + 2 * tg;
      Od[d * OSTR + rq] = accO[set][nt][0] * inv0;
      Od[(d + 1) * OSTR + rq] = accO[set][nt][1] * inv0;
      Od[d * OSTR + rq + 8] = accO[set][nt][2] * inv1;
      Od[(d + 1) * OSTR + rq + 8] = accO[set][nt][3] * inv1;
    }
  }
  __syncthreads();
  {
    int d = tid >> 1;
    int c0 = (tid & 1) * 64;
    float* ao = AO + ((size_t)b * CH + (size_t)h * 64 + d) * TT + q0 + c0;
#pragma unroll
    for (int i = 0; i < 16; i++) {
      float4 o4 = *(float4*)&Od[d * OSTR + c0 + i * 4];
      *(float4*)&ao[i * 4] = o4;
    }
  }
}

// ---------------------------------------------------------------------------
extern "C" void kernel_launch(void* const* d_in, const int* in_sizes, int n_in,
                              void* d_out, int out_size) {
  const float* x    = (const float*)d_in[0];
  const float* ctx  = (const float*)d_in[1];
  const int*   mask = (const int*)d_in[2];
  const float* Wq   = (const float*)d_in[3];
  const float* bq   = (const float*)d_in[4];
  const float* Wk   = (const float*)d_in[5];
  const float* bk   = (const float*)d_in[6];
  const float* Wv   = (const float*)d_in[7];
  const float* bv   = (const float*)d_in[8];
  const float* Wo   = (const float*)d_in[9];
  const float* bo   = (const float*)d_in[10];
  float* out = (float*)d_out;

  float *p, *q, *k, *v;
  cudaGetSymbolAddress((void**)&p, g_p);
  cudaGetSymbolAddress((void**)&q, g_q);
  cudaGetSymbolAddress((void**)&k, g_k);
  cudaGetSymbolAddress((void**)&v, g_v);

  cudaFuncSetAttribute(attn_mma, cudaFuncAttributeMaxDynamicSharedMemorySize,
                       ATT_SMEM);

  dim3 gqkv(TT / 128, CH / 128, BSZ * 3);
  dim3 go(TT / 128, CH / 128, BSZ);
  dim3 ag(TT / 128, NH, BSZ);

  gemm_qkv<<<gqkv, 256>>>(x, ctx, Wq, bq, Wk, bk, Wv, bv, q, k, v);
  attn_mma<<<ag, 128, ATT_SMEM>>>(q, k, v, mask, p);
  gemm_o<<<go, 256>>>(Wo, p, bo, out);
}